// round 6
// baseline (speedup 1.0000x reference)
#include <cuda_runtime.h>

#define BN    2048
#define DD    32
#define NIDS  8192
#define KNN   30
#define TI    8
#define JPT   4
#define NTHR  256
#define JH    (NTHR * JPT)              // 1024
#define YSPL  2
#define XCTA  (BN / TI)                 // 256
#define NCTAS_ALL (XCTA * (YSPL + 1))   // 768
#define BCAP  16

// Scratch (no allocations allowed)
__device__ float g_sq[BN];
__device__ float g_zT[DD * BN];
__device__ float g_pden[YSPL * BN];
__device__ float g_num[BN];
__device__ float g_any[BN];
__device__ float g_diag[BN];
__device__ int   g_bkt[NIDS * BCAP];
__device__ int   g_bcnt[NIDS];          // ids never present stay 0 forever
__device__ unsigned g_cnt = 0;

__device__ __forceinline__ unsigned long long pack2(float x, float y) {
    unsigned long long r;
    asm("mov.b64 %0, {%1, %2};" : "=l"(r) : "f"(x), "f"(y));
    return r;
}
__device__ __forceinline__ void unpack2(unsigned long long v, float &x, float &y) {
    asm("mov.b64 {%0, %1}, %2;" : "=f"(x), "=f"(y) : "l"(v));
}
__device__ __forceinline__ unsigned long long fma2(unsigned long long a,
                                                   unsigned long long b,
                                                   unsigned long long c) {
    unsigned long long d;
    asm("fma.rn.f32x2 %0, %1, %2, %3;" : "=l"(d) : "l"(a), "l"(b), "l"(c));
    return d;
}
__device__ __forceinline__ float fsqrt_approx(float x) {
    float r;
    asm("sqrt.approx.f32 %0, %1;" : "=f"(r) : "f"(x));
    return r;
}
// single shared expression so both kernels' codegen matches bit-exactly
__device__ __forceinline__ float pair_e(float dot, float sqsum) {
    float d2 = fmaf(-2.f, dot, sqsum);
    d2 = fmaxf(d2, 1e-20f);
    return __expf(-fsqrt_approx(d2));
}

// Kernel 1: grid 320 CTAs.
//  bid<256 : transpose z->zT + row norms (coalesced).
//  bid>=256: build deterministic inverse buckets  id -> sorted list of j with sid[j]==id.
__global__ void __launch_bounds__(NTHR)
prep_kernel(const float* __restrict__ z, const int* __restrict__ sid) {
    __shared__ float sf[8 * 33];
    __shared__ int ssid[BN];
    __shared__ int s_c1[32][8];
    __shared__ int s_c2[32][8];
    const int t = threadIdx.x;

    if (blockIdx.x < 256) {
        const int idx = blockIdx.x * NTHR + t;
        const float v = __ldg(&z[idx]);
        float s = v * v;
#pragma unroll
        for (int off = 16; off > 0; off >>= 1)
            s += __shfl_xor_sync(0xffffffffu, s, off);
        if ((t & 31) == 0) g_sq[idx >> 5] = s;
        sf[(t >> 5) * 33 + (t & 31)] = v;
        __syncthreads();
        const int k2 = t >> 3;
        const int jo = t & 7;
        g_zT[k2 * BN + blockIdx.x * 8 + jo] = sf[jo * 33 + k2];
    } else {
        const int bb = blockIdx.x - 256;           // 0..63, 32 j's each
        for (int w = t; w < BN; w += NTHR) ssid[w] = sid[w];
        __syncthreads();
        const int jl = t >> 3;                     // 0..31
        const int c = t & 7;                       // chunk 0..7
        const int j = bb * 32 + jl;
        const int myid = ssid[j];
        int c1 = 0, c2 = 0;
        const int base = c * 256;
#pragma unroll 8
        for (int q = 0; q < 256; q++) {
            int s2 = ssid[base + q];
            bool mt = (s2 == myid);
            c2 += mt ? 1 : 0;
            c1 += (mt && (base + q < j)) ? 1 : 0;
        }
        s_c1[jl][c] = c1;
        s_c2[jl][c] = c2;
        __syncthreads();
        if (t < 32) {
            int j2 = bb * 32 + t;
            int rank = 0, count = 0;
#pragma unroll
            for (int cc = 0; cc < 8; cc++) { rank += s_c1[t][cc]; count += s_c2[t][cc]; }
            int id = ssid[j2];
            if (rank < BCAP) g_bkt[id * BCAP + rank] = j2;  // rank order => sorted by j
            g_bcnt[id] = count;                              // same value from all writers
        }
    }
}

// Kernel 2: grid (256, 3).
//  y<2 : den slice — rows [x*8,+8) vs j in [y*1024,+1024), each thread 4 j's.
//  y==2: sparse num/valid/diag — warp per row via inverse buckets.
// Last of 768 CTAs does the final scalar reduction.
__global__ void __launch_bounds__(NTHR, 4)
main_kernel(const float* __restrict__ z,
            const int* __restrict__ knn,
            const int* __restrict__ sid,
            float* __restrict__ out) {
    __shared__ unsigned long long s_zd[DD * TI];   // duplicated z_i: u64(v,v) at k*TI+r
    __shared__ float s_sqi[TI];
    __shared__ float s_rd[NTHR / 32][TI];
    __shared__ bool s_last;

    const int t = threadIdx.x;
    const int y = blockIdx.y;
    const int warp = t >> 5, lane = t & 31;

    if (y < YSPL) {
        const int row0 = blockIdx.x * TI;
        const int j0 = y * JH;
        {   // fill duplicated tile (256 entries, one per thread)
            int k = t & 31, r = t >> 5;
            float v = z[(row0 + r) * DD + k];
            s_zd[k * TI + r] = pack2(v, v);
        }
        if (t < TI) s_sqi[t] = g_sq[row0 + t];
        __syncthreads();

        const int j = j0 + t * JPT;
        unsigned long long acc[TI][2];
#pragma unroll
        for (int r = 0; r < TI; r++) { acc[r][0] = 0ull; acc[r][1] = 0ull; }

#pragma unroll 4
        for (int k = 0; k < DD; k++) {
            ulonglong2 v = *(const ulonglong2*)(g_zT + k * BN + j);  // (j0,j1),(j2,j3)
#pragma unroll
            for (int r = 0; r < TI; r++) {
                unsigned long long zr = s_zd[k * TI + r];            // broadcast LDS
                acc[r][0] = fma2(zr, v.x, acc[r][0]);
                acc[r][1] = fma2(zr, v.y, acc[r][1]);
            }
        }

        const float4 sqjv = *(const float4*)(g_sq + j);
        float den[TI];
#pragma unroll
        for (int r = 0; r < TI; r++) {
            float d0, d1, d2, d3;
            unpack2(acc[r][0], d0, d1);
            unpack2(acc[r][1], d2, d3);
            float base = s_sqi[r];
            float e0 = pair_e(d0, base + sqjv.x);
            float e1 = pair_e(d1, base + sqjv.y);
            float e2 = pair_e(d2, base + sqjv.z);
            float e3 = pair_e(d3, base + sqjv.w);
            den[r] = (e0 + e1) + (e2 + e3);
        }
#pragma unroll
        for (int r = 0; r < TI; r++) {
#pragma unroll
            for (int off = 16; off > 0; off >>= 1)
                den[r] += __shfl_xor_sync(0xffffffffu, den[r], off);
        }
        if (lane == 0) {
#pragma unroll
            for (int r = 0; r < TI; r++) s_rd[warp][r] = den[r];
        }
        __syncthreads();
        if (t < TI) {
            float dsum = 0.f;
#pragma unroll
            for (int w = 0; w < NTHR / 32; w++) dsum += s_rd[w][t];
            g_pden[y * BN + row0 + t] = dsum;   // includes diag e_ii; subtracted later
        }
    } else {
        // ---- sparse num / valid / diag: warp per row ----
        const int i = blockIdx.x * TI + warp;
        const int sidi = sid[i];
        int id = (lane < KNN) ? knn[sidi * KNN + lane] : -1;
        bool dup = false;
#pragma unroll
        for (int p = 0; p < KNN; p++) {
            int idp = __shfl_sync(0xffffffffu, id, p);
            dup = dup || (p < lane && idp == id);
        }
        float num = 0.f;
        bool found = false;
        if (lane < KNN && !dup) {
            int cnt = g_bcnt[id];
            if (cnt > BCAP) cnt = BCAP;
            for (int s = 0; s < cnt; s++) {
                int jj = g_bkt[id * BCAP + s];
                if (jj != i) {
                    const float* zi = z + i * DD;
                    const float* zj = z + jj * DD;
                    float dot = 0.f;
#pragma unroll
                    for (int k = 0; k < DD; k++) dot = fmaf(zi[k], zj[k], dot);
                    num += pair_e(dot, g_sq[i] + g_sq[jj]);
                    found = true;
                }
            }
        }
#pragma unroll
        for (int off = 16; off > 0; off >>= 1)
            num += __shfl_xor_sync(0xffffffffu, num, off);
        unsigned bal = __ballot_sync(0xffffffffu, found);
        if (lane == 0) {
            // e_ii, bit-identical to the den path's diagonal term
            const float* zi = z + i * DD;
            float dot = 0.f;
#pragma unroll
            for (int k = 0; k < DD; k++) dot = fmaf(zi[k], zi[k], dot);
            g_diag[i] = pair_e(dot, g_sq[i] + g_sq[i]);
            g_num[i] = num;
            g_any[i] = bal ? 1.f : 0.f;
        }
    }

    // ---- last-block final reduction (deterministic) ----
    __threadfence();
    if (t == 0) {
        unsigned old = atomicAdd(&g_cnt, 1u);
        s_last = (old == NCTAS_ALL - 1);
    }
    __syncthreads();
    if (!s_last) return;

    __threadfence();
    float tot = 0.f, cnt = 0.f;
#pragma unroll
    for (int i = t; i < BN; i += NTHR) {
        float den = (__ldcg(&g_pden[i]) + __ldcg(&g_pden[BN + i])) - __ldcg(&g_diag[i]);
        float nv = __ldcg(&g_num[i]);
        bool valid = __ldcg(&g_any[i]) > 0.f;
        float sr = nv / den;
        float loss = -__logf(sr + 1e-8f);
        tot += valid ? loss : 0.f;
        cnt += valid ? 1.f : 0.f;
    }
#pragma unroll
    for (int off = 16; off > 0; off >>= 1) {
        tot += __shfl_xor_sync(0xffffffffu, tot, off);
        cnt += __shfl_xor_sync(0xffffffffu, cnt, off);
    }
    if (lane == 0) { s_rd[warp][0] = tot; s_rd[warp][1] = cnt; }
    __syncthreads();
    if (t == 0) {
        float T = 0.f, C = 0.f;
#pragma unroll
        for (int w = 0; w < NTHR / 32; w++) { T += s_rd[w][0]; C += s_rd[w][1]; }
        out[0] = (C > 0.f) ? (T / C) : 0.f;
        g_cnt = 0;  // reset for next graph replay
    }
}

extern "C" void kernel_launch(void* const* d_in, const int* in_sizes, int n_in,
                              void* d_out, int out_size) {
    const float* z   = (const float*)d_in[0];
    const int*   knn = (const int*)d_in[1];
    const int*   sid = (const int*)d_in[2];
    (void)in_sizes; (void)n_in; (void)out_size;

    prep_kernel<<<256 + 64, NTHR>>>(z, sid);
    main_kernel<<<dim3(XCTA, YSPL + 1, 1), NTHR>>>(z, knn, sid, (float*)d_out);
}

// round 7
// speedup vs baseline: 1.3597x; 1.3597x over previous
#include <cuda_runtime.h>

#define BN    2048
#define DD    32
#define NIDS  8192
#define KNN   30
#define TI    8
#define JPT   4
#define NTHR  256
#define JH    (NTHR * JPT)              // 1024
#define YSPL  2
#define XCTA  (BN / TI)                 // 256
#define NCTAS_ALL (XCTA * (YSPL + 1))   // 768
#define BCAP  32

// Scratch (no allocations allowed)
__device__ float g_sq[BN];
__device__ float g_zT[DD * BN];
__device__ float g_pden[YSPL * BN];
__device__ float g_num[BN];
__device__ float g_any[BN];
__device__ float g_diag[BN];
__device__ int   g_bkt[NIDS * BCAP];
__device__ int   g_bcnt[NIDS];          // zero-init at load; re-zeroed by main's last block
__device__ unsigned g_cnt = 0;

__device__ __forceinline__ unsigned long long pack2(float x, float y) {
    unsigned long long r;
    asm("mov.b64 %0, {%1, %2};" : "=l"(r) : "f"(x), "f"(y));
    return r;
}
__device__ __forceinline__ void unpack2(unsigned long long v, float &x, float &y) {
    asm("mov.b64 {%0, %1}, %2;" : "=f"(x), "=f"(y) : "l"(v));
}
__device__ __forceinline__ unsigned long long fma2(unsigned long long a,
                                                   unsigned long long b,
                                                   unsigned long long c) {
    unsigned long long d;
    asm("fma.rn.f32x2 %0, %1, %2, %3;" : "=l"(d) : "l"(a), "l"(b), "l"(c));
    return d;
}
__device__ __forceinline__ float fsqrt_approx(float x) {
    float r;
    asm("sqrt.approx.f32 %0, %1;" : "=f"(r) : "f"(x));
    return r;
}
// shared expression so den-path and sparse/diag-path codegen matches bit-exactly
__device__ __forceinline__ float pair_e(float dot, float sqsum) {
    float d2 = fmaf(-2.f, dot, sqsum);
    d2 = fmaxf(d2, 1e-20f);
    return __expf(-fsqrt_approx(d2));
}

// Kernel 1: grid 264 CTAs.
//  bid<256 : transpose z->zT + row norms (coalesced).
//  bid>=256: atomic bucket fill  id -> {j : sid[j]==id}  (order nondet; sorted at use).
__global__ void __launch_bounds__(NTHR)
prep_kernel(const float* __restrict__ z, const int* __restrict__ sid) {
    __shared__ float sf[8 * 33];
    const int t = threadIdx.x;

    if (blockIdx.x < 256) {
        const int idx = blockIdx.x * NTHR + t;
        const float v = __ldg(&z[idx]);
        float s = v * v;
#pragma unroll
        for (int off = 16; off > 0; off >>= 1)
            s += __shfl_xor_sync(0xffffffffu, s, off);
        if ((t & 31) == 0) g_sq[idx >> 5] = s;
        sf[(t >> 5) * 33 + (t & 31)] = v;
        __syncthreads();
        const int k2 = t >> 3;
        const int jo = t & 7;
        g_zT[k2 * BN + blockIdx.x * 8 + jo] = sf[jo * 33 + k2];
    } else {
        const int j = (blockIdx.x - 256) * NTHR + t;   // 8 CTAs cover 2048 j's
        const int id = sid[j];
        int slot = atomicAdd(&g_bcnt[id], 1);
        if (slot < BCAP) g_bkt[id * BCAP + slot] = j;
    }
}

// Kernel 2: grid (256, 3).
//  y<2 : den slice — rows [x*8,+8) vs j in [y*1024,+1024), each thread 4 j's, no mask.
//  y==2: sparse num/valid/diag via inverse buckets — warp per row.
// Last of 768 CTAs: final scalar reduction + scratch reset.
__global__ void __launch_bounds__(NTHR, 4)
main_kernel(const float* __restrict__ z,
            const int* __restrict__ knn,
            const int* __restrict__ sid,
            float* __restrict__ out) {
    // z_i row-pairs: u64 index k*4+p = (zi[2p][k], zi[2p+1][k]) -> 1KB
    __shared__ unsigned long long s_zi[DD * (TI / 2)];
    __shared__ float s_sqi[TI];
    __shared__ float s_rd[NTHR / 32][TI];
    __shared__ bool s_last;

    const int t = threadIdx.x;
    const int y = blockIdx.y;
    const int warp = t >> 5, lane = t & 31;

    if (y < YSPL) {
        const int row0 = blockIdx.x * TI;
        const int j0 = y * JH;
        {   // fill z_i tile (256 floats): sf[k*TI + r]
            float* sf = (float*)s_zi;
            int k = t & 31, r = t >> 5;
            sf[k * TI + r] = z[(row0 + r) * DD + k];
        }
        if (t < TI) s_sqi[t] = g_sq[row0 + t];
        __syncthreads();

        const int j = j0 + t * JPT;
        unsigned long long acc[TI / 2][JPT];
#pragma unroll
        for (int p = 0; p < TI / 2; p++)
#pragma unroll
            for (int q = 0; q < JPT; q++) acc[p][q] = 0ull;

        const float4* zT4 = (const float4*)g_zT;
#pragma unroll 4
        for (int k = 0; k < DD; k++) {
            float4 vj = zT4[(k * BN + j) >> 2];   // one LDG.128 = 4 j's
            unsigned long long v0 = pack2(vj.x, vj.x);
            unsigned long long v1 = pack2(vj.y, vj.y);
            unsigned long long v2 = pack2(vj.z, vj.z);
            unsigned long long v3 = pack2(vj.w, vj.w);
#pragma unroll
            for (int p = 0; p < TI / 2; p++) {
                unsigned long long zp = s_zi[k * (TI / 2) + p];
                acc[p][0] = fma2(zp, v0, acc[p][0]);
                acc[p][1] = fma2(zp, v1, acc[p][1]);
                acc[p][2] = fma2(zp, v2, acc[p][2]);
                acc[p][3] = fma2(zp, v3, acc[p][3]);
            }
        }

        const float4 sqjv = *(const float4*)(g_sq + j);
        const float sqj[JPT] = {sqjv.x, sqjv.y, sqjv.z, sqjv.w};
        float den[TI];
#pragma unroll
        for (int p = 0; p < TI / 2; p++) {
            float d0[JPT], d1[JPT];
#pragma unroll
            for (int q = 0; q < JPT; q++) unpack2(acc[p][q], d0[q], d1[q]);
#pragma unroll
            for (int rr = 0; rr < 2; rr++) {
                int r = 2 * p + rr;
                float base = s_sqi[r];
                float e0 = pair_e(rr ? d1[0] : d0[0], base + sqj[0]);
                float e1 = pair_e(rr ? d1[1] : d0[1], base + sqj[1]);
                float e2 = pair_e(rr ? d1[2] : d0[2], base + sqj[2]);
                float e3 = pair_e(rr ? d1[3] : d0[3], base + sqj[3]);
                den[r] = (e0 + e1) + (e2 + e3);   // includes diag term; subtracted later
            }
        }
#pragma unroll
        for (int r = 0; r < TI; r++) {
#pragma unroll
            for (int off = 16; off > 0; off >>= 1)
                den[r] += __shfl_xor_sync(0xffffffffu, den[r], off);
        }
        if (lane == 0) {
#pragma unroll
            for (int r = 0; r < TI; r++) s_rd[warp][r] = den[r];
        }
        __syncthreads();
        if (t < TI) {
            float dsum = 0.f;
#pragma unroll
            for (int w = 0; w < NTHR / 32; w++) dsum += s_rd[w][t];
            g_pden[y * BN + row0 + t] = dsum;
        }
    } else {
        // ---- sparse num / valid / diag: warp per row (cold path) ----
        const int i = blockIdx.x * TI + warp;
        const int sidi = sid[i];
        int id = (lane < KNN) ? knn[sidi * KNN + lane] : -1;
        bool dup = false;
#pragma unroll
        for (int p = 0; p < KNN; p++) {
            int idp = __shfl_sync(0xffffffffu, id, p);
            dup = dup || (p < lane && idp == id);
        }
        float num = 0.f;
        bool found = false;
        if (lane < KNN && !dup) {
            int cnt = g_bcnt[id];
            if (cnt > BCAP) cnt = BCAP;
            if (cnt > 0) {
                int jarr[BCAP];
                for (int s = 0; s < cnt; s++) jarr[s] = g_bkt[id * BCAP + s];
                // insertion sort ascending -> deterministic summation order
                for (int a = 1; a < cnt; a++) {
                    int v = jarr[a];
                    int b = a - 1;
                    while (b >= 0 && jarr[b] > v) { jarr[b + 1] = jarr[b]; b--; }
                    jarr[b + 1] = v;
                }
                for (int s = 0; s < cnt; s++) {
                    int jj = jarr[s];
                    if (jj != i) {
                        const float* zi = z + i * DD;
                        const float* zj = z + jj * DD;
                        float dot = 0.f;
#pragma unroll
                        for (int k = 0; k < DD; k++) dot = fmaf(zi[k], zj[k], dot);
                        num += pair_e(dot, g_sq[i] + g_sq[jj]);
                        found = true;
                    }
                }
            }
        }
#pragma unroll
        for (int off = 16; off > 0; off >>= 1)
            num += __shfl_xor_sync(0xffffffffu, num, off);
        unsigned bal = __ballot_sync(0xffffffffu, found);
        if (lane == 0) {
            // e_ii: sequential fmaf chain == FFMA2 lane chain bit-exactly
            const float* zi = z + i * DD;
            float dot = 0.f;
#pragma unroll
            for (int k = 0; k < DD; k++) dot = fmaf(zi[k], zi[k], dot);
            g_diag[i] = pair_e(dot, g_sq[i] + g_sq[i]);
            g_num[i] = num;
            g_any[i] = bal ? 1.f : 0.f;
        }
    }

    // ---- last-block final reduction (deterministic) ----
    __threadfence();
    if (t == 0) {
        unsigned old = atomicAdd(&g_cnt, 1u);
        s_last = (old == NCTAS_ALL - 1);
    }
    __syncthreads();
    if (!s_last) return;

    __threadfence();
    float tot = 0.f, cnt = 0.f;
#pragma unroll
    for (int i = t; i < BN; i += NTHR) {
        float den = (__ldcg(&g_pden[i]) + __ldcg(&g_pden[BN + i])) - __ldcg(&g_diag[i]);
        float nv = __ldcg(&g_num[i]);
        bool valid = __ldcg(&g_any[i]) > 0.f;
        float sr = nv / den;
        float loss = -__logf(sr + 1e-8f);
        tot += valid ? loss : 0.f;
        cnt += valid ? 1.f : 0.f;
    }
#pragma unroll
    for (int off = 16; off > 0; off >>= 1) {
        tot += __shfl_xor_sync(0xffffffffu, tot, off);
        cnt += __shfl_xor_sync(0xffffffffu, cnt, off);
    }
    if (lane == 0) { s_rd[warp][0] = tot; s_rd[warp][1] = cnt; }
    __syncthreads();
    if (t == 0) {
        float T = 0.f, C = 0.f;
#pragma unroll
        for (int w = 0; w < NTHR / 32; w++) { T += s_rd[w][0]; C += s_rd[w][1]; }
        out[0] = (C > 0.f) ? (T / C) : 0.f;
        g_cnt = 0;
    }
    // reset bucket counters for the next replay (zero-init covers the first call)
    for (int i = t; i < NIDS; i += NTHR) g_bcnt[i] = 0;
}

extern "C" void kernel_launch(void* const* d_in, const int* in_sizes, int n_in,
                              void* d_out, int out_size) {
    const float* z   = (const float*)d_in[0];
    const int*   knn = (const int*)d_in[1];
    const int*   sid = (const int*)d_in[2];
    (void)in_sizes; (void)n_in; (void)out_size;

    prep_kernel<<<256 + BN / NTHR, NTHR>>>(z, sid);
    main_kernel<<<dim3(XCTA, YSPL + 1, 1), NTHR>>>(z, knn, sid, (float*)d_out);
}

// round 8
// speedup vs baseline: 1.4558x; 1.0707x over previous
#include <cuda_runtime.h>

#define BN    2048
#define DD    32
#define NIDS  8192
#define KNN   30
#define TI    8
#define JPT   4
#define NTHR  256
#define JH    (NTHR * JPT)              // 1024
#define YSPL  2
#define XCTA  (BN / TI)                 // 256
#define NCTAS_ALL (XCTA * (YSPL + 1))   // 768
#define BCAP  32

// Scratch (no allocations allowed)
__device__ float g_sq[BN];
__device__ float g_zT[DD * BN];
__device__ float g_pden[YSPL * BN];
__device__ float g_num[BN];
__device__ float g_any[BN];
__device__ float g_diag[BN];
__device__ int   g_bkt[NIDS * BCAP];
__device__ int   g_bcnt[NIDS];          // zero-init at load; re-zeroed by main's last block
__device__ unsigned g_cnt = 0;

__device__ __forceinline__ unsigned long long pack2(float x, float y) {
    unsigned long long r;
    asm("mov.b64 %0, {%1, %2};" : "=l"(r) : "f"(x), "f"(y));
    return r;
}
__device__ __forceinline__ void unpack2(unsigned long long v, float &x, float &y) {
    asm("mov.b64 {%0, %1}, %2;" : "=f"(x), "=f"(y) : "l"(v));
}
__device__ __forceinline__ unsigned long long fma2(unsigned long long a,
                                                   unsigned long long b,
                                                   unsigned long long c) {
    unsigned long long d;
    asm("fma.rn.f32x2 %0, %1, %2, %3;" : "=l"(d) : "l"(a), "l"(b), "l"(c));
    return d;
}
__device__ __forceinline__ float fsqrt_approx(float x) {
    float r;
    asm("sqrt.approx.f32 %0, %1;" : "=f"(r) : "f"(x));
    return r;
}
// shared expression so den-path and sparse/diag-path codegen matches bit-exactly
__device__ __forceinline__ float pair_e(float dot, float sqsum) {
    float d2 = fmaf(-2.f, dot, sqsum);
    d2 = fmaxf(d2, 1e-20f);
    return __expf(-fsqrt_approx(d2));
}

// Kernel 1: grid 264 CTAs.
//  bid<256 : transpose z->zT + row norms (coalesced).
//  bid>=256: atomic bucket fill  id -> {j : sid[j]==id}  (order nondet; sorted at use).
__global__ void __launch_bounds__(NTHR)
prep_kernel(const float* __restrict__ z, const int* __restrict__ sid) {
    __shared__ float sf[8 * 33];
    const int t = threadIdx.x;

    if (blockIdx.x < 256) {
        const int idx = blockIdx.x * NTHR + t;
        const float v = __ldg(&z[idx]);
        float s = v * v;
#pragma unroll
        for (int off = 16; off > 0; off >>= 1)
            s += __shfl_xor_sync(0xffffffffu, s, off);
        if ((t & 31) == 0) g_sq[idx >> 5] = s;
        sf[(t >> 5) * 33 + (t & 31)] = v;
        __syncthreads();
        const int k2 = t >> 3;
        const int jo = t & 7;
        g_zT[k2 * BN + blockIdx.x * 8 + jo] = sf[jo * 33 + k2];
    } else {
        const int j = (blockIdx.x - 256) * NTHR + t;   // 8 CTAs cover 2048 j's
        const int id = sid[j];
        int slot = atomicAdd(&g_bcnt[id], 1);
        if (slot < BCAP) g_bkt[id * BCAP + slot] = j;
    }
}

// Kernel 2: grid (256, 3).
//  y<2 : den slice — rows [x*8,+8) vs j in [y*1024,+1024), each thread 4 j's, no mask.
//  y==2: sparse num/valid/diag via inverse buckets — warp per row.
// Last of 768 CTAs: final scalar reduction + scratch reset.
__global__ void __launch_bounds__(NTHR, 3)
main_kernel(const float* __restrict__ z,
            const int* __restrict__ knn,
            const int* __restrict__ sid,
            float* __restrict__ out) {
    // z_i row-pairs: u64 index k*4+p = (zi[2p][k], zi[2p+1][k]) -> 1KB
    __shared__ unsigned long long s_zi[DD * (TI / 2)];
    __shared__ float s_sqi[TI];
    __shared__ float s_rd[NTHR / 32][TI];
    __shared__ bool s_last;

    const int t = threadIdx.x;
    const int y = blockIdx.y;
    const int warp = t >> 5, lane = t & 31;

    if (y < YSPL) {
        const int row0 = blockIdx.x * TI;
        const int j0 = y * JH;
        {   // fill z_i tile (256 floats): sf[k*TI + r]
            float* sf = (float*)s_zi;
            int k = t & 31, r = t >> 5;
            sf[k * TI + r] = z[(row0 + r) * DD + k];
        }
        if (t < TI) s_sqi[t] = g_sq[row0 + t];
        __syncthreads();

        const int j = j0 + t * JPT;
        unsigned long long acc[TI / 2][JPT];
#pragma unroll
        for (int p = 0; p < TI / 2; p++)
#pragma unroll
            for (int q = 0; q < JPT; q++) acc[p][q] = 0ull;

        const float4* zT4 = (const float4*)g_zT;
#pragma unroll 8
        for (int k = 0; k < DD; k++) {
            float4 vj = zT4[(k * BN + j) >> 2];   // one LDG.128 = 4 j's
            unsigned long long v0 = pack2(vj.x, vj.x);
            unsigned long long v1 = pack2(vj.y, vj.y);
            unsigned long long v2 = pack2(vj.z, vj.z);
            unsigned long long v3 = pack2(vj.w, vj.w);
#pragma unroll
            for (int p = 0; p < TI / 2; p++) {
                unsigned long long zp = s_zi[k * (TI / 2) + p];
                acc[p][0] = fma2(zp, v0, acc[p][0]);
                acc[p][1] = fma2(zp, v1, acc[p][1]);
                acc[p][2] = fma2(zp, v2, acc[p][2]);
                acc[p][3] = fma2(zp, v3, acc[p][3]);
            }
        }

        const float4 sqjv = *(const float4*)(g_sq + j);
        const float sqj[JPT] = {sqjv.x, sqjv.y, sqjv.z, sqjv.w};
        float den[TI];
#pragma unroll
        for (int p = 0; p < TI / 2; p++) {
            float d0[JPT], d1[JPT];
#pragma unroll
            for (int q = 0; q < JPT; q++) unpack2(acc[p][q], d0[q], d1[q]);
#pragma unroll
            for (int rr = 0; rr < 2; rr++) {
                int r = 2 * p + rr;
                float base = s_sqi[r];
                float e0 = pair_e(rr ? d1[0] : d0[0], base + sqj[0]);
                float e1 = pair_e(rr ? d1[1] : d0[1], base + sqj[1]);
                float e2 = pair_e(rr ? d1[2] : d0[2], base + sqj[2]);
                float e3 = pair_e(rr ? d1[3] : d0[3], base + sqj[3]);
                den[r] = (e0 + e1) + (e2 + e3);   // includes diag term; subtracted later
            }
        }
#pragma unroll
        for (int r = 0; r < TI; r++) {
#pragma unroll
            for (int off = 16; off > 0; off >>= 1)
                den[r] += __shfl_xor_sync(0xffffffffu, den[r], off);
        }
        if (lane == 0) {
#pragma unroll
            for (int r = 0; r < TI; r++) s_rd[warp][r] = den[r];
        }
        __syncthreads();
        if (t < TI) {
            float dsum = 0.f;
#pragma unroll
            for (int w = 0; w < NTHR / 32; w++) dsum += s_rd[w][t];
            g_pden[y * BN + row0 + t] = dsum;
        }
    } else {
        // ---- sparse num / valid / diag: warp per row (cold path) ----
        const int i = blockIdx.x * TI + warp;
        const int sidi = sid[i];
        int id = (lane < KNN) ? knn[sidi * KNN + lane] : -1;
        bool dup = false;
#pragma unroll
        for (int p = 0; p < KNN; p++) {
            int idp = __shfl_sync(0xffffffffu, id, p);
            dup = dup || (p < lane && idp == id);
        }
        float num = 0.f;
        bool found = false;
        if (lane < KNN && !dup) {
            int cnt = g_bcnt[id];
            if (cnt > BCAP) cnt = BCAP;
            if (cnt > 0) {
                int jarr[BCAP];
                for (int s = 0; s < cnt; s++) jarr[s] = g_bkt[id * BCAP + s];
                // insertion sort ascending -> deterministic summation order
                for (int a = 1; a < cnt; a++) {
                    int v = jarr[a];
                    int b = a - 1;
                    while (b >= 0 && jarr[b] > v) { jarr[b + 1] = jarr[b]; b--; }
                    jarr[b + 1] = v;
                }
                for (int s = 0; s < cnt; s++) {
                    int jj = jarr[s];
                    if (jj != i) {
                        const float* zi = z + i * DD;
                        const float* zj = z + jj * DD;
                        float dot = 0.f;
#pragma unroll
                        for (int k = 0; k < DD; k++) dot = fmaf(zi[k], zj[k], dot);
                        num += pair_e(dot, g_sq[i] + g_sq[jj]);
                        found = true;
                    }
                }
            }
        }
#pragma unroll
        for (int off = 16; off > 0; off >>= 1)
            num += __shfl_xor_sync(0xffffffffu, num, off);
        unsigned bal = __ballot_sync(0xffffffffu, found);
        if (lane == 0) {
            // e_ii: sequential fmaf chain == FFMA2 lane chain bit-exactly
            const float* zi = z + i * DD;
            float dot = 0.f;
#pragma unroll
            for (int k = 0; k < DD; k++) dot = fmaf(zi[k], zi[k], dot);
            g_diag[i] = pair_e(dot, g_sq[i] + g_sq[i]);
            g_num[i] = num;
            g_any[i] = bal ? 1.f : 0.f;
        }
    }

    // ---- last-block final reduction (deterministic) ----
    __threadfence();
    if (t == 0) {
        unsigned old = atomicAdd(&g_cnt, 1u);
        s_last = (old == NCTAS_ALL - 1);
    }
    __syncthreads();
    if (!s_last) return;

    __threadfence();
    float tot = 0.f, cnt = 0.f;
#pragma unroll
    for (int i = t; i < BN; i += NTHR) {
        float den = (__ldcg(&g_pden[i]) + __ldcg(&g_pden[BN + i])) - __ldcg(&g_diag[i]);
        float nv = __ldcg(&g_num[i]);
        bool valid = __ldcg(&g_any[i]) > 0.f;
        float sr = nv / den;
        float loss = -__logf(sr + 1e-8f);
        tot += valid ? loss : 0.f;
        cnt += valid ? 1.f : 0.f;
    }
#pragma unroll
    for (int off = 16; off > 0; off >>= 1) {
        tot += __shfl_xor_sync(0xffffffffu, tot, off);
        cnt += __shfl_xor_sync(0xffffffffu, cnt, off);
    }
    if (lane == 0) { s_rd[warp][0] = tot; s_rd[warp][1] = cnt; }
    __syncthreads();
    if (t == 0) {
        float T = 0.f, C = 0.f;
#pragma unroll
        for (int w = 0; w < NTHR / 32; w++) { T += s_rd[w][0]; C += s_rd[w][1]; }
        out[0] = (C > 0.f) ? (T / C) : 0.f;
        g_cnt = 0;
    }
    // reset bucket counters for the next replay (zero-init covers the first call)
    for (int i = t; i < NIDS; i += NTHR) g_bcnt[i] = 0;
}

extern "C" void kernel_launch(void* const* d_in, const int* in_sizes, int n_in,
                              void* d_out, int out_size) {
    const float* z   = (const float*)d_in[0];
    const int*   knn = (const int*)d_in[1];
    const int*   sid = (const int*)d_in[2];
    (void)in_sizes; (void)n_in; (void)out_size;

    prep_kernel<<<256 + BN / NTHR, NTHR>>>(z, sid);
    main_kernel<<<dim3(XCTA, YSPL + 1, 1), NTHR>>>(z, knn, sid, (float*)d_out);
}

// round 9
// speedup vs baseline: 1.4576x; 1.0013x over previous
#include <cuda_runtime.h>

#define BN    2048
#define DD    32
#define NIDS  8192
#define KNN   30
#define TI    8
#define JPT   4
#define NTHR  256
#define JH    (NTHR * JPT)              // 1024
#define YSPL  2
#define XCTA  (BN / TI)                 // 256
#define NCTAS_ALL (XCTA * (YSPL + 1))   // 768
#define BCAP  32

// Scratch (no allocations allowed)
__device__ float g_sq[BN];
__device__ float g_zT[DD * BN];
__device__ float g_pden[YSPL * BN];
__device__ float g_num[BN];
__device__ float g_any[BN];
__device__ float g_diag[BN];
__device__ int   g_bkt[NIDS * BCAP];
__device__ int   g_bcnt[NIDS];          // zero-init at load; re-zeroed by main's last block
__device__ unsigned g_cnt = 0;

__device__ __forceinline__ unsigned long long pack2(float x, float y) {
    unsigned long long r;
    asm("mov.b64 %0, {%1, %2};" : "=l"(r) : "f"(x), "f"(y));
    return r;
}
__device__ __forceinline__ void unpack2(unsigned long long v, float &x, float &y) {
    asm("mov.b64 {%0, %1}, %2;" : "=f"(x), "=f"(y) : "l"(v));
}
__device__ __forceinline__ unsigned long long fma2(unsigned long long a,
                                                   unsigned long long b,
                                                   unsigned long long c) {
    unsigned long long d;
    asm("fma.rn.f32x2 %0, %1, %2, %3;" : "=l"(d) : "l"(a), "l"(b), "l"(c));
    return d;
}
__device__ __forceinline__ float fsqrt_approx(float x) {
    float r;
    asm("sqrt.approx.f32 %0, %1;" : "=f"(r) : "f"(x));
    return r;
}
// shared expression so den-path and sparse/diag-path codegen matches bit-exactly
__device__ __forceinline__ float pair_e(float dot, float sqsum) {
    float d2 = fmaf(-2.f, dot, sqsum);
    d2 = fmaxf(d2, 1e-20f);
    return __expf(-fsqrt_approx(d2));
}

// Kernel 1: grid 264 CTAs.
//  bid<256 : transpose z->zT + row norms (coalesced).
//  bid>=256: atomic bucket fill  id -> {j : sid[j]==id}  (order nondet; sorted at use).
__global__ void __launch_bounds__(NTHR)
prep_kernel(const float* __restrict__ z, const int* __restrict__ sid) {
    __shared__ float sf[8 * 33];
    const int t = threadIdx.x;

    if (blockIdx.x < 256) {
        const int idx = blockIdx.x * NTHR + t;
        const float v = __ldg(&z[idx]);
        float s = v * v;
#pragma unroll
        for (int off = 16; off > 0; off >>= 1)
            s += __shfl_xor_sync(0xffffffffu, s, off);
        if ((t & 31) == 0) g_sq[idx >> 5] = s;
        sf[(t >> 5) * 33 + (t & 31)] = v;
        __syncthreads();
        const int k2 = t >> 3;
        const int jo = t & 7;
        g_zT[k2 * BN + blockIdx.x * 8 + jo] = sf[jo * 33 + k2];
    } else {
        const int j = (blockIdx.x - 256) * NTHR + t;   // 8 CTAs cover 2048 j's
        const int id = sid[j];
        int slot = atomicAdd(&g_bcnt[id], 1);
        if (slot < BCAP) g_bkt[id * BCAP + slot] = j;
    }
}

// Kernel 2: grid (256, 3).
//  y<2 : den slice — rows [x*8,+8) vs j in [y*1024,+1024), 4 j's/thread,
//        software-pipelined LDG (depth 4) + LDS.128 tile reads.
//  y==2: sparse num/valid/diag via inverse buckets — warp per row.
// Last of 768 CTAs: final scalar reduction + scratch reset.
__global__ void __launch_bounds__(NTHR, 3)
main_kernel(const float* __restrict__ z,
            const int* __restrict__ knn,
            const int* __restrict__ sid,
            float* __restrict__ out) {
    // z_i row-pairs: u64 index k*4+p = (zi[2p][k], zi[2p+1][k]) -> 1KB, 16B-aligned rows
    __shared__ __align__(16) unsigned long long s_zi[DD * (TI / 2)];
    __shared__ float s_sqi[TI];
    __shared__ float s_rd[NTHR / 32][TI];
    __shared__ bool s_last;

    const int t = threadIdx.x;
    const int y = blockIdx.y;
    const int warp = t >> 5, lane = t & 31;

    if (y < YSPL) {
        const int row0 = blockIdx.x * TI;
        const int j0 = y * JH;
        {   // fill z_i tile (256 floats): sf[k*TI + r]
            float* sf = (float*)s_zi;
            int k = t & 31, r = t >> 5;
            sf[k * TI + r] = z[(row0 + r) * DD + k];
        }
        if (t < TI) s_sqi[t] = g_sq[row0 + t];
        __syncthreads();

        const int j = j0 + t * JPT;
        unsigned long long acc[TI / 2][JPT];
#pragma unroll
        for (int p = 0; p < TI / 2; p++)
#pragma unroll
            for (int q = 0; q < JPT; q++) acc[p][q] = 0ull;

        // ---- software-pipelined k-loop: prefetch depth 4, forced MLP=4 ----
        const float4* pj = (const float4*)(g_zT + j);   // row stride = BN/4 float4
        float4 buf[4];
#pragma unroll
        for (int k = 0; k < 4; k++) buf[k] = pj[k * (BN / 4)];

#pragma unroll
        for (int k = 0; k < DD; k++) {
            float4 vj = buf[k & 3];
            if (k + 4 < DD) buf[k & 3] = pj[(k + 4) * (BN / 4)];

            unsigned long long v0 = pack2(vj.x, vj.x);
            unsigned long long v1 = pack2(vj.y, vj.y);
            unsigned long long v2 = pack2(vj.z, vj.z);
            unsigned long long v3 = pack2(vj.w, vj.w);

            // two LDS.128: row-pairs (p0,p1) and (p2,p3) for this k
            ulonglong2 zp01 = *(const ulonglong2*)&s_zi[k * 4 + 0];
            ulonglong2 zp23 = *(const ulonglong2*)&s_zi[k * 4 + 2];

            acc[0][0] = fma2(zp01.x, v0, acc[0][0]);
            acc[0][1] = fma2(zp01.x, v1, acc[0][1]);
            acc[0][2] = fma2(zp01.x, v2, acc[0][2]);
            acc[0][3] = fma2(zp01.x, v3, acc[0][3]);
            acc[1][0] = fma2(zp01.y, v0, acc[1][0]);
            acc[1][1] = fma2(zp01.y, v1, acc[1][1]);
            acc[1][2] = fma2(zp01.y, v2, acc[1][2]);
            acc[1][3] = fma2(zp01.y, v3, acc[1][3]);
            acc[2][0] = fma2(zp23.x, v0, acc[2][0]);
            acc[2][1] = fma2(zp23.x, v1, acc[2][1]);
            acc[2][2] = fma2(zp23.x, v2, acc[2][2]);
            acc[2][3] = fma2(zp23.x, v3, acc[2][3]);
            acc[3][0] = fma2(zp23.y, v0, acc[3][0]);
            acc[3][1] = fma2(zp23.y, v1, acc[3][1]);
            acc[3][2] = fma2(zp23.y, v2, acc[3][2]);
            acc[3][3] = fma2(zp23.y, v3, acc[3][3]);
        }

        const float4 sqjv = *(const float4*)(g_sq + j);
        const float sqj[JPT] = {sqjv.x, sqjv.y, sqjv.z, sqjv.w};
        float den[TI];
#pragma unroll
        for (int p = 0; p < TI / 2; p++) {
            float d0[JPT], d1[JPT];
#pragma unroll
            for (int q = 0; q < JPT; q++) unpack2(acc[p][q], d0[q], d1[q]);
#pragma unroll
            for (int rr = 0; rr < 2; rr++) {
                int r = 2 * p + rr;
                float base = s_sqi[r];
                float e0 = pair_e(rr ? d1[0] : d0[0], base + sqj[0]);
                float e1 = pair_e(rr ? d1[1] : d0[1], base + sqj[1]);
                float e2 = pair_e(rr ? d1[2] : d0[2], base + sqj[2]);
                float e3 = pair_e(rr ? d1[3] : d0[3], base + sqj[3]);
                den[r] = (e0 + e1) + (e2 + e3);   // includes diag term; subtracted later
            }
        }
#pragma unroll
        for (int r = 0; r < TI; r++) {
#pragma unroll
            for (int off = 16; off > 0; off >>= 1)
                den[r] += __shfl_xor_sync(0xffffffffu, den[r], off);
        }
        if (lane == 0) {
#pragma unroll
            for (int r = 0; r < TI; r++) s_rd[warp][r] = den[r];
        }
        __syncthreads();
        if (t < TI) {
            float dsum = 0.f;
#pragma unroll
            for (int w = 0; w < NTHR / 32; w++) dsum += s_rd[w][t];
            g_pden[y * BN + row0 + t] = dsum;
        }
    } else {
        // ---- sparse num / valid / diag: warp per row (cold path) ----
        const int i = blockIdx.x * TI + warp;
        const int sidi = sid[i];
        int id = (lane < KNN) ? knn[sidi * KNN + lane] : -1;
        bool dup = false;
#pragma unroll
        for (int p = 0; p < KNN; p++) {
            int idp = __shfl_sync(0xffffffffu, id, p);
            dup = dup || (p < lane && idp == id);
        }
        float num = 0.f;
        bool found = false;
        if (lane < KNN && !dup) {
            int cnt = g_bcnt[id];
            if (cnt > BCAP) cnt = BCAP;
            if (cnt > 0) {
                int jarr[BCAP];
                for (int s = 0; s < cnt; s++) jarr[s] = g_bkt[id * BCAP + s];
                // insertion sort ascending -> deterministic summation order
                for (int a = 1; a < cnt; a++) {
                    int v = jarr[a];
                    int b = a - 1;
                    while (b >= 0 && jarr[b] > v) { jarr[b + 1] = jarr[b]; b--; }
                    jarr[b + 1] = v;
                }
                for (int s = 0; s < cnt; s++) {
                    int jj = jarr[s];
                    if (jj != i) {
                        const float* zi = z + i * DD;
                        const float* zj = z + jj * DD;
                        float dot = 0.f;
#pragma unroll
                        for (int k = 0; k < DD; k++) dot = fmaf(zi[k], zj[k], dot);
                        num += pair_e(dot, g_sq[i] + g_sq[jj]);
                        found = true;
                    }
                }
            }
        }
#pragma unroll
        for (int off = 16; off > 0; off >>= 1)
            num += __shfl_xor_sync(0xffffffffu, num, off);
        unsigned bal = __ballot_sync(0xffffffffu, found);
        if (lane == 0) {
            // e_ii: sequential fmaf chain == FFMA2 lane chain bit-exactly
            const float* zi = z + i * DD;
            float dot = 0.f;
#pragma unroll
            for (int k = 0; k < DD; k++) dot = fmaf(zi[k], zi[k], dot);
            g_diag[i] = pair_e(dot, g_sq[i] + g_sq[i]);
            g_num[i] = num;
            g_any[i] = bal ? 1.f : 0.f;
        }
    }

    // ---- last-block final reduction (deterministic) ----
    __threadfence();
    if (t == 0) {
        unsigned old = atomicAdd(&g_cnt, 1u);
        s_last = (old == NCTAS_ALL - 1);
    }
    __syncthreads();
    if (!s_last) return;

    __threadfence();
    float tot = 0.f, cnt = 0.f;
#pragma unroll
    for (int i = t; i < BN; i += NTHR) {
        float den = (__ldcg(&g_pden[i]) + __ldcg(&g_pden[BN + i])) - __ldcg(&g_diag[i]);
        float nv = __ldcg(&g_num[i]);
        bool valid = __ldcg(&g_any[i]) > 0.f;
        float sr = nv / den;
        float loss = -__logf(sr + 1e-8f);
        tot += valid ? loss : 0.f;
        cnt += valid ? 1.f : 0.f;
    }
#pragma unroll
    for (int off = 16; off > 0; off >>= 1) {
        tot += __shfl_xor_sync(0xffffffffu, tot, off);
        cnt += __shfl_xor_sync(0xffffffffu, cnt, off);
    }
    if (lane == 0) { s_rd[warp][0] = tot; s_rd[warp][1] = cnt; }
    __syncthreads();
    if (t == 0) {
        float T = 0.f, C = 0.f;
#pragma unroll
        for (int w = 0; w < NTHR / 32; w++) { T += s_rd[w][0]; C += s_rd[w][1]; }
        out[0] = (C > 0.f) ? (T / C) : 0.f;
        g_cnt = 0;
    }
    // reset bucket counters for the next replay (zero-init covers the first call)
    for (int i = t; i < NIDS; i += NTHR) g_bcnt[i] = 0;
}

extern "C" void kernel_launch(void* const* d_in, const int* in_sizes, int n_in,
                              void* d_out, int out_size) {
    const float* z   = (const float*)d_in[0];
    const int*   knn = (const int*)d_in[1];
    const int*   sid = (const int*)d_in[2];
    (void)in_sizes; (void)n_in; (void)out_size;

    prep_kernel<<<256 + BN / NTHR, NTHR>>>(z, sid);
    main_kernel<<<dim3(XCTA, YSPL + 1, 1), NTHR>>>(z, knn, sid, (float*)d_out);
}